// round 1
// baseline (speedup 1.0000x reference)
#include <cuda_runtime.h>

#define NN 131072
#define GG 1024
#define EE 4194304
#define DD 128

// ---------------- scratch (device globals; no allocation allowed) ----------
__device__ float devDis[NN];          // deg^{-1/2} (incl. self-loop)
__device__ float devInv[NN];          // 1/deg
__device__ int   devDeg[NN];
__device__ float devH [NN * 32];      // h = in @ W          (pre-aggregation)
__device__ float devGm[NN * 32];      // g = dis * h         (scatter payload)
__device__ float devT [NN * 32];      // t = sum_{edges} g[src]
__device__ float devA [NN * 32];      // activation ping
__device__ float devBf[NN * 32];      // activation pong
__device__ float devPooled[GG * 288]; // per-graph concat features

// ---------------- degree + normalization ----------------------------------
__global__ void k_zero_deg() {
    int i = blockIdx.x * blockDim.x + threadIdx.x;
    if (i < NN) devDeg[i] = 0;
}

__global__ void k_deg(const int* __restrict__ dst) {
    int e = blockIdx.x * blockDim.x + threadIdx.x;
    if (e < EE) atomicAdd(&devDeg[dst[e]], 1);
}

__global__ void k_dis() {
    int i = blockIdx.x * blockDim.x + threadIdx.x;
    if (i < NN) {
        float d = (float)(devDeg[i] + 1);   // +1 self-loop
        devDis[i] = rsqrtf(d);
        devInv[i] = 1.0f / d;
    }
}

// ---------------- GEMM: h = in @ W, g = dis*h  (N x K  @  K x 32) ----------
// Block: 256 threads (32 cols x 8 rows), 8 rows per block.
template <int K>
__global__ void k_gemm(const float* __restrict__ xext,
                       const float* __restrict__ W, int insel) {
    __shared__ float Ws[K * 32];
    __shared__ float xs[8 * K];
    const float* in = (insel == 0) ? xext : (insel == 1 ? devA : devBf);

    int tid = threadIdx.x;
    for (int i = tid; i < K * 32; i += 256) Ws[i] = W[i];
    int rowbase = blockIdx.x * 8;
    for (int i = tid; i < 8 * K; i += 256) xs[i] = in[rowbase * K + i];
    __syncthreads();

    int tx = tid & 31, ty = tid >> 5;
    float acc = 0.f;
#pragma unroll
    for (int k = 0; k < K; k++)
        acc = fmaf(xs[ty * K + k], Ws[k * 32 + tx], acc);

    int row = rowbase + ty;
    devH [row * 32 + tx] = acc;
    devGm[row * 32 + tx] = devDis[row] * acc;
}

// ---------------- zero accumulator -----------------------------------------
__global__ void k_zero_t() {
    int i = blockIdx.x * blockDim.x + threadIdx.x;   // NN*32/4 float4 slots
    ((float4*)devT)[i] = make_float4(0.f, 0.f, 0.f, 0.f);
}

// ---------------- edge scatter: t[dst] += g[src] ---------------------------
// 8 threads per edge, one float4 each (vector atomic on sm_90+).
__global__ void k_edge(const int* __restrict__ src, const int* __restrict__ dst) {
    int idx = blockIdx.x * blockDim.x + threadIdx.x;   // exactly EE*8 threads
    int e = idx >> 3, q = idx & 7;
    int s = __ldg(&src[e]);
    int d = __ldg(&dst[e]);
    float4 v = *(const float4*)&devGm[s * 32 + q * 4];
#if __CUDA_ARCH__ >= 900
    atomicAdd((float4*)&devT[d * 32 + q * 4], v);
#else
    float* p = &devT[d * 32 + q * 4];
    atomicAdd(p + 0, v.x); atomicAdd(p + 1, v.y);
    atomicAdd(p + 2, v.z); atomicAdd(p + 3, v.w);
#endif
}

// ---------------- combine: act = tanh(dis*t + inv*h + b), pool row 0 -------
__global__ void k_combine(const float* __restrict__ bias, int poolBase, int outsel) {
    int i = blockIdx.x * blockDim.x + threadIdx.x;
    if (i < NN * 32) {
        int n = i >> 5, c = i & 31;
        float v = tanhf(devDis[n] * devT[i] + devInv[n] * devH[i] + bias[c]);
        float* act = outsel ? devBf : devA;
        act[i] = v;
        if ((n & 127) == 0)                          // first node of each graph
            devPooled[(n >> 7) * 288 + poolBase + c] = v;
    }
}

// ---------------- head ------------------------------------------------------
__global__ void k_head_init(float* out) {
    out[2048] = 0.f;   // loss
    out[2049] = 0.f;   // acc
}

// 1024 blocks x 128 threads: hidden = cat @ W1 + b1 ; logits/loss/acc
__global__ void k_head(const float* __restrict__ W1, const float* __restrict__ b1,
                       const float* __restrict__ W2, const float* __restrict__ b2,
                       const int* __restrict__ y, float* __restrict__ out) {
    __shared__ float cs[288];
    __shared__ float red[8];
    int g = blockIdx.x, t = threadIdx.x;

    for (int i = t; i < 288; i += 128) cs[i] = devPooled[g * 288 + i];
    __syncthreads();

    float acc = b1[t];
#pragma unroll 8
    for (int k = 0; k < 288; k++)
        acc = fmaf(cs[k], W1[k * 128 + t], acc);

    out[2050 + g * 128 + t] = acc;          // feature (pre-ReLU hidden)
    float hr = fmaxf(acc, 0.f);
    float p0 = hr * W2[t * 2 + 0];
    float p1 = hr * W2[t * 2 + 1];
    for (int o = 16; o; o >>= 1) {
        p0 += __shfl_down_sync(0xFFFFFFFFu, p0, o);
        p1 += __shfl_down_sync(0xFFFFFFFFu, p1, o);
    }
    int w = t >> 5;
    if ((t & 31) == 0) { red[w] = p0; red[4 + w] = p1; }
    __syncthreads();

    if (t == 0) {
        float z0 = red[0] + red[1] + red[2] + red[3] + b2[0];
        float z1 = red[4] + red[5] + red[6] + red[7] + b2[1];
        float m  = fmaxf(z0, z1);
        float lse = m + logf(expf(z0 - m) + expf(z1 - m));
        float l0 = z0 - lse, l1 = z1 - lse;
        out[g * 2 + 0] = l0;
        out[g * 2 + 1] = l1;
        int yy = y[g];
        atomicAdd(&out[2048], -(yy ? l1 : l0) * (1.0f / GG));
        int pred = (l1 > l0) ? 1 : 0;        // argmax ties -> index 0
        if (pred == yy) atomicAdd(&out[2049], 1.0f / GG);
    }
}

// ---------------- launch -----------------------------------------------------
extern "C" void kernel_launch(void* const* d_in, const int* in_sizes, int n_in,
                              void* d_out, int out_size) {
    const float* x[3]  = { (const float*)d_in[0], (const float*)d_in[3], (const float*)d_in[6] };
    const int*   ei[3] = { (const int*)  d_in[1], (const int*)  d_in[4], (const int*)  d_in[7] };
    const int*   y     = (const int*)d_in[9];
    const float* Wc[3] = { (const float*)d_in[10], (const float*)d_in[12], (const float*)d_in[14] };
    const float* bc[3] = { (const float*)d_in[11], (const float*)d_in[13], (const float*)d_in[15] };
    const float* W1 = (const float*)d_in[16];
    const float* b1 = (const float*)d_in[17];
    const float* W2 = (const float*)d_in[18];
    const float* b2 = (const float*)d_in[19];
    float* out = (float*)d_out;

    for (int b = 0; b < 3; b++) {
        const int* src = ei[b];
        const int* dst = ei[b] + EE;

        k_zero_deg<<<NN / 256, 256>>>();
        k_deg<<<EE / 256, 256>>>(dst);
        k_dis<<<NN / 256, 256>>>();

        for (int l = 0; l < 3; l++) {
            // insel: layer0 <- external x, layer1 <- devA, layer2 <- devBf
            if (l == 0)      k_gemm<128><<<NN / 8, 256>>>(x[b], Wc[0], 0);
            else if (l == 1) k_gemm<32> <<<NN / 8, 256>>>(nullptr, Wc[1], 1);
            else             k_gemm<32> <<<NN / 8, 256>>>(nullptr, Wc[2], 2);

            k_zero_t<<<(NN * 32 / 4) / 256, 256>>>();
            k_edge<<<(EE * 8) / 256, 256>>>(src, dst);

            // outsel: layer0 -> devA, layer1 -> devBf, layer2 -> devA
            int outsel = (l == 1) ? 1 : 0;
            k_combine<<<(NN * 32) / 256, 256>>>(bc[l], b * 96 + l * 32, outsel);
        }
    }

    k_head_init<<<1, 1>>>(out);
    k_head<<<GG, 128>>>(W1, b1, W2, b2, y, out);
}

// round 2
// speedup vs baseline: 1.6034x; 1.6034x over previous
#include <cuda_runtime.h>

#define NN 131072
#define GG 1024
#define EE 4194304
#define DD 128

// ---------------- scratch (device globals; no allocation allowed) ----------
__device__ float devDis[NN];           // deg^{-1/2} (incl. self-loop)
__device__ int   devDeg[NN];
__device__ int   devOff[NN];           // CSR exclusive offsets
__device__ int   devCur[NN];           // fill cursors
__device__ int   devBlk[512];          // scan block sums
__device__ int   devCsr[EE];           // src list grouped by dst
__device__ float devGm[NN * 32];       // g = dis * (in @ W)
__device__ float devA [NN * 32];       // activation ping
__device__ float devBf[NN * 32];       // activation pong
__device__ float devPooled[GG * 288];  // per-graph concat features

// ---------------- degree -----------------------------------------------------
__global__ void k_zero_deg() {
    int i = blockIdx.x * blockDim.x + threadIdx.x;
    if (i < NN) devDeg[i] = 0;
}

__global__ void k_deg(const int* __restrict__ dst) {
    int e = blockIdx.x * blockDim.x + threadIdx.x;
    if (e < EE) atomicAdd(&devDeg[dst[e]], 1);
}

// ---------------- exclusive scan of devDeg -> devOff/devCur ------------------
__global__ void k_scan1() {               // 512 blocks x 256 threads
    __shared__ int sh[256];
    int tid = threadIdx.x;
    int i = blockIdx.x * 256 + tid;
    int v = devDeg[i];
    sh[tid] = v;
    __syncthreads();
#pragma unroll
    for (int o = 1; o < 256; o <<= 1) {
        int t = (tid >= o) ? sh[tid - o] : 0;
        __syncthreads();
        sh[tid] += t;
        __syncthreads();
    }
    devOff[i] = sh[tid] - v;              // block-local exclusive
    if (tid == 255) devBlk[blockIdx.x] = sh[255];
}

__global__ void k_scan2() {               // 1 block x 512 threads
    __shared__ int sh[512];
    int tid = threadIdx.x;
    int v = devBlk[tid];
    sh[tid] = v;
    __syncthreads();
#pragma unroll
    for (int o = 1; o < 512; o <<= 1) {
        int t = (tid >= o) ? sh[tid - o] : 0;
        __syncthreads();
        sh[tid] += t;
        __syncthreads();
    }
    devBlk[tid] = sh[tid] - v;            // exclusive block offsets
}

__global__ void k_scan3() {               // finalize offsets + dis
    int i = blockIdx.x * blockDim.x + threadIdx.x;
    if (i < NN) {
        int off = devOff[i] + devBlk[i >> 8];
        devOff[i] = off;
        devCur[i] = off;
        devDis[i] = rsqrtf((float)(devDeg[i] + 1));   // +1 self-loop
    }
}

// ---------------- CSR fill ---------------------------------------------------
__global__ void k_csr_fill(const int* __restrict__ src, const int* __restrict__ dst) {
    int e = blockIdx.x * blockDim.x + threadIdx.x;
    if (e < EE) {
        int p = atomicAdd(&devCur[dst[e]], 1);
        devCsr[p] = src[e];
    }
}

// ---------------- GEMM: g = dis * (in @ W)  (N x K @ K x 32) -----------------
// Block: 256 threads, tile 32 rows x 32 cols, each thread -> 1 row x 4 cols.
template <int K>
__global__ void k_gemm(const float* __restrict__ xext,
                       const float* __restrict__ W, int insel) {
    __shared__ float4 Ws[K * 8];          // W as [K][8] float4
    __shared__ float  xs[32 * K];
    const float* in = (insel == 0) ? xext : (insel == 1 ? devA : devBf);

    int tid = threadIdx.x;
    for (int i = tid; i < K * 8; i += 256) Ws[i] = ((const float4*)W)[i];
    int rowbase = blockIdx.x * 32;
    const float4* xin = (const float4*)(in + rowbase * K);
    for (int i = tid; i < 32 * K / 4; i += 256) ((float4*)xs)[i] = xin[i];
    __syncthreads();

    int tx = tid & 7, ty = tid >> 3;
    float4 acc = make_float4(0.f, 0.f, 0.f, 0.f);
#pragma unroll
    for (int k = 0; k < K; k++) {
        float  xv = xs[ty * K + k];
        float4 w  = Ws[k * 8 + tx];
        acc.x = fmaf(xv, w.x, acc.x);
        acc.y = fmaf(xv, w.y, acc.y);
        acc.z = fmaf(xv, w.z, acc.z);
        acc.w = fmaf(xv, w.w, acc.w);
    }
    int row = rowbase + ty;
    float s = devDis[row];
    acc.x *= s; acc.y *= s; acc.z *= s; acc.w *= s;
    ((float4*)devGm)[row * 8 + tx] = acc;
}

// ---------------- fused aggregation + combine + pool -------------------------
// One warp per node: act[n] = tanh(dis[n] * (sum_{src->n} g[src] + g[n]) + b)
__global__ void k_aggr(const float* __restrict__ bias, int poolBase, int outsel) {
    int gtid = blockIdx.x * blockDim.x + threadIdx.x;
    int n = gtid >> 5;
    int lane = gtid & 31;

    int off = devOff[n];
    int end = off + devDeg[n];

    float a0 = devGm[n * 32 + lane];      // self-loop term (dis*h folded)
    float a1 = 0.f, a2 = 0.f, a3 = 0.f;

    for (int base = off; base < end; base += 32) {
        int p = base + lane;
        int idx = (p < end) ? devCsr[p] : 0;
        int cnt = min(end - base, 32);
        int j = 0;
        for (; j + 3 < cnt; j += 4) {
            int s0 = __shfl_sync(0xFFFFFFFFu, idx, j);
            int s1 = __shfl_sync(0xFFFFFFFFu, idx, j + 1);
            int s2 = __shfl_sync(0xFFFFFFFFu, idx, j + 2);
            int s3 = __shfl_sync(0xFFFFFFFFu, idx, j + 3);
            a0 += devGm[s0 * 32 + lane];
            a1 += devGm[s1 * 32 + lane];
            a2 += devGm[s2 * 32 + lane];
            a3 += devGm[s3 * 32 + lane];
        }
        for (; j < cnt; j++) {
            int s = __shfl_sync(0xFFFFFFFFu, idx, j);
            a0 += devGm[s * 32 + lane];
        }
    }

    float v = tanhf(devDis[n] * (((a0 + a1) + (a2 + a3))) + bias[lane]);
    float* act = outsel ? devBf : devA;
    act[n * 32 + lane] = v;
    if ((n & 127) == 0)                   // first node of each graph
        devPooled[(n >> 7) * 288 + poolBase + lane] = v;
}

// ---------------- head -------------------------------------------------------
__global__ void k_head_init(float* out) {
    out[2048] = 0.f;   // loss
    out[2049] = 0.f;   // acc
}

__global__ void k_head(const float* __restrict__ W1, const float* __restrict__ b1,
                       const float* __restrict__ W2, const float* __restrict__ b2,
                       const int* __restrict__ y, float* __restrict__ out) {
    __shared__ float cs[288];
    __shared__ float red[8];
    int g = blockIdx.x, t = threadIdx.x;

    for (int i = t; i < 288; i += 128) cs[i] = devPooled[g * 288 + i];
    __syncthreads();

    float acc = b1[t];
#pragma unroll 8
    for (int k = 0; k < 288; k++)
        acc = fmaf(cs[k], W1[k * 128 + t], acc);

    out[2050 + g * 128 + t] = acc;          // feature (pre-ReLU hidden)
    float hr = fmaxf(acc, 0.f);
    float p0 = hr * W2[t * 2 + 0];
    float p1 = hr * W2[t * 2 + 1];
    for (int o = 16; o; o >>= 1) {
        p0 += __shfl_down_sync(0xFFFFFFFFu, p0, o);
        p1 += __shfl_down_sync(0xFFFFFFFFu, p1, o);
    }
    int w = t >> 5;
    if ((t & 31) == 0) { red[w] = p0; red[4 + w] = p1; }
    __syncthreads();

    if (t == 0) {
        float z0 = red[0] + red[1] + red[2] + red[3] + b2[0];
        float z1 = red[4] + red[5] + red[6] + red[7] + b2[1];
        float m  = fmaxf(z0, z1);
        float lse = m + logf(expf(z0 - m) + expf(z1 - m));
        float l0 = z0 - lse, l1 = z1 - lse;
        out[g * 2 + 0] = l0;
        out[g * 2 + 1] = l1;
        int yy = y[g];
        atomicAdd(&out[2048], -(yy ? l1 : l0) * (1.0f / GG));
        int pred = (l1 > l0) ? 1 : 0;
        if (pred == yy) atomicAdd(&out[2049], 1.0f / GG);
    }
}

// ---------------- launch -----------------------------------------------------
extern "C" void kernel_launch(void* const* d_in, const int* in_sizes, int n_in,
                              void* d_out, int out_size) {
    const float* x[3]  = { (const float*)d_in[0], (const float*)d_in[3], (const float*)d_in[6] };
    const int*   ei[3] = { (const int*)  d_in[1], (const int*)  d_in[4], (const int*)  d_in[7] };
    const int*   y     = (const int*)d_in[9];
    const float* Wc[3] = { (const float*)d_in[10], (const float*)d_in[12], (const float*)d_in[14] };
    const float* bc[3] = { (const float*)d_in[11], (const float*)d_in[13], (const float*)d_in[15] };
    const float* W1 = (const float*)d_in[16];
    const float* b1 = (const float*)d_in[17];
    const float* W2 = (const float*)d_in[18];
    const float* b2 = (const float*)d_in[19];
    float* out = (float*)d_out;

    for (int b = 0; b < 3; b++) {
        const int* src = ei[b];
        const int* dst = ei[b] + EE;

        k_zero_deg<<<NN / 256, 256>>>();
        k_deg<<<EE / 256, 256>>>(dst);
        k_scan1<<<512, 256>>>();
        k_scan2<<<1, 512>>>();
        k_scan3<<<NN / 256, 256>>>();
        k_csr_fill<<<EE / 256, 256>>>(src, dst);

        for (int l = 0; l < 3; l++) {
            if (l == 0)      k_gemm<128><<<NN / 32, 256>>>(x[b], Wc[0], 0);
            else if (l == 1) k_gemm<32> <<<NN / 32, 256>>>(nullptr, Wc[1], 1);
            else             k_gemm<32> <<<NN / 32, 256>>>(nullptr, Wc[2], 2);

            // l0 -> devA, l1 -> devBf, l2 -> devA
            int outsel = (l == 1) ? 1 : 0;
            k_aggr<<<(NN * 32) / 256, 256>>>(bc[l], b * 96 + l * 32, outsel);
        }
    }

    k_head_init<<<1, 1>>>(out);
    k_head<<<GG, 128>>>(W1, b1, W2, b2, y, out);
}

// round 3
// speedup vs baseline: 1.7304x; 1.0792x over previous
#include <cuda_runtime.h>

#define NN 131072
#define GG 1024
#define EE 4194304
#define DD 128

// ---------------- scratch (device globals; no allocation allowed) ----------
__device__ float devDis[NN];           // deg^{-1/2} (incl. self-loop)
__device__ int   devDeg[NN];
__device__ int   devOff[NN];           // CSR exclusive offsets
__device__ int   devCur[NN];           // fill cursors
__device__ int   devBlk[512];          // scan block sums
__device__ int   devCsr[EE];           // src list grouped by dst
__device__ float devG0[NN * 32];       // scatter payload ping
__device__ float devG1[NN * 32];       // scatter payload pong
__device__ float devPooled[GG * 288];  // per-graph concat features

// ---------------- degree -----------------------------------------------------
__global__ void k_zero_deg() {
    int i = blockIdx.x * blockDim.x + threadIdx.x;
    if (i < NN) devDeg[i] = 0;
}

__global__ void k_deg(const int* __restrict__ dst) {
    int e = blockIdx.x * blockDim.x + threadIdx.x;
    if (e < EE) atomicAdd(&devDeg[dst[e]], 1);
}

// ---------------- exclusive scan of devDeg -> devOff/devCur ------------------
__global__ void k_scan1() {               // 512 blocks x 256 threads
    __shared__ int sh[256];
    int tid = threadIdx.x;
    int i = blockIdx.x * 256 + tid;
    int v = devDeg[i];
    sh[tid] = v;
    __syncthreads();
#pragma unroll
    for (int o = 1; o < 256; o <<= 1) {
        int t = (tid >= o) ? sh[tid - o] : 0;
        __syncthreads();
        sh[tid] += t;
        __syncthreads();
    }
    devOff[i] = sh[tid] - v;              // block-local exclusive
    if (tid == 255) devBlk[blockIdx.x] = sh[255];
}

__global__ void k_scan2() {               // 1 block x 512 threads
    __shared__ int sh[512];
    int tid = threadIdx.x;
    int v = devBlk[tid];
    sh[tid] = v;
    __syncthreads();
#pragma unroll
    for (int o = 1; o < 512; o <<= 1) {
        int t = (tid >= o) ? sh[tid - o] : 0;
        __syncthreads();
        sh[tid] += t;
        __syncthreads();
    }
    devBlk[tid] = sh[tid] - v;            // exclusive block offsets
}

__global__ void k_scan3() {               // finalize offsets + dis
    int i = blockIdx.x * blockDim.x + threadIdx.x;
    if (i < NN) {
        int off = devOff[i] + devBlk[i >> 8];
        devOff[i] = off;
        devCur[i] = off;
        devDis[i] = rsqrtf((float)(devDeg[i] + 1));   // +1 self-loop
    }
}

// ---------------- CSR fill ---------------------------------------------------
__global__ void k_csr_fill(const int* __restrict__ src, const int* __restrict__ dst) {
    int e = blockIdx.x * blockDim.x + threadIdx.x;
    if (e < EE) {
        int p = atomicAdd(&devCur[dst[e]], 1);
        devCsr[p] = src[e];
    }
}

// ---------------- first-layer GEMM: devG0 = dis * (x @ Wc0) ------------------
// Block 256 threads, tile 128 rows x 32 cols, 4 rows x 4 cols per thread,
// K=128 staged in chunks of 32.
__global__ void k_gemm128(const float* __restrict__ x, const float* __restrict__ W) {
    __shared__ float Ws[128 * 32];        // full W (16 KB)
    __shared__ float xs[128 * 33];        // 128 rows x 32 K-chunk, pad 33

    int tid = threadIdx.x;
    int rowbase = blockIdx.x * 128;

    for (int i = tid; i < 128 * 32 / 4; i += 256)
        ((float4*)Ws)[i] = ((const float4*)W)[i];

    int tx = tid & 7, ty = tid >> 3;      // tx: colgroup (4 cols), ty: row 0..31
    float4 acc[4];
#pragma unroll
    for (int m = 0; m < 4; m++) acc[m] = make_float4(0.f, 0.f, 0.f, 0.f);

    int lrow = tid >> 3;                  // 0..31 (row within chunk load)... reuse
    for (int c = 0; c < 4; c++) {
        // load x rows [rowbase..rowbase+128), K cols [c*32, c*32+32)
        // thread t: row = t/8, f4 = t%8 covers 8 float4 per 32-col row... 128 rows
        for (int r = tid >> 3; r < 128; r += 32) {
            float4 v = *(const float4*)&x[(rowbase + r) * 128 + c * 32 + (tid & 7) * 4];
            float* p = &xs[r * 33 + (tid & 7) * 4];
            p[0] = v.x; p[1] = v.y; p[2] = v.z; p[3] = v.w;
        }
        __syncthreads();
#pragma unroll
        for (int k = 0; k < 32; k++) {
            float4 w = ((const float4*)&Ws[(c * 32 + k) * 32])[tx];
#pragma unroll
            for (int m = 0; m < 4; m++) {
                float xv = xs[(ty + 32 * m) * 33 + k];
                acc[m].x = fmaf(xv, w.x, acc[m].x);
                acc[m].y = fmaf(xv, w.y, acc[m].y);
                acc[m].z = fmaf(xv, w.z, acc[m].z);
                acc[m].w = fmaf(xv, w.w, acc[m].w);
            }
        }
        __syncthreads();
    }

#pragma unroll
    for (int m = 0; m < 4; m++) {
        int row = rowbase + ty + 32 * m;
        float s = devDis[row];
        acc[m].x *= s; acc[m].y *= s; acc[m].z *= s; acc[m].w *= s;
        ((float4*)devG0)[row * 8 + tx] = acc[m];
    }
}

// ---------------- fused aggregation + tanh + next-layer matvec + pool --------
// One warp per node. v = tanh(dis*(sum g[src] + g[n]) + b).
// If FUSE: gout[n] = dis[n] * (v @ Wnext)  (payload for next layer's scatter).
template <bool FUSE>
__global__ void k_aggr(const float* __restrict__ bias,
                       const float* __restrict__ Wnext,
                       int poolBase, int ginsel) {
    __shared__ float Ws[32 * 32];
    const float* gin  = ginsel ? devG1 : devG0;
    float*       gout = ginsel ? devG0 : devG1;

    if (FUSE) {
        for (int i = threadIdx.x; i < 32 * 32 / 4; i += 256)
            ((float4*)Ws)[i] = ((const float4*)Wnext)[i];
        __syncthreads();
    }

    int gtid = blockIdx.x * blockDim.x + threadIdx.x;
    int n = gtid >> 5;
    int lane = gtid & 31;

    int off = devOff[n];
    int end = off + devDeg[n];

    float a0 = gin[n * 32 + lane];        // self-loop term (dis*h folded)
    float a1 = 0.f, a2 = 0.f, a3 = 0.f;

    for (int base = off; base < end; base += 32) {
        int p = base + lane;
        int idx = (p < end) ? devCsr[p] : 0;
        int cnt = min(end - base, 32);
        int j = 0;
        for (; j + 3 < cnt; j += 4) {
            int s0 = __shfl_sync(0xFFFFFFFFu, idx, j);
            int s1 = __shfl_sync(0xFFFFFFFFu, idx, j + 1);
            int s2 = __shfl_sync(0xFFFFFFFFu, idx, j + 2);
            int s3 = __shfl_sync(0xFFFFFFFFu, idx, j + 3);
            a0 += gin[s0 * 32 + lane];
            a1 += gin[s1 * 32 + lane];
            a2 += gin[s2 * 32 + lane];
            a3 += gin[s3 * 32 + lane];
        }
        for (; j < cnt; j++) {
            int s = __shfl_sync(0xFFFFFFFFu, idx, j);
            a0 += gin[s * 32 + lane];
        }
    }

    float dis = devDis[n];
    float v = tanhf(dis * ((a0 + a1) + (a2 + a3)) + bias[lane]);

    if ((n & 127) == 0)                   // first node of each graph
        devPooled[(n >> 7) * 288 + poolBase + lane] = v;

    if (FUSE) {
        float acc = 0.f;
#pragma unroll
        for (int k = 0; k < 32; k++) {
            float vk = __shfl_sync(0xFFFFFFFFu, v, k);
            acc = fmaf(vk, Ws[k * 32 + lane], acc);
        }
        gout[n * 32 + lane] = dis * acc;
    }
}

// ---------------- head -------------------------------------------------------
__global__ void k_head_init(float* out) {
    out[2048] = 0.f;   // loss
    out[2049] = 0.f;   // acc
}

__global__ void k_head(const float* __restrict__ W1, const float* __restrict__ b1,
                       const float* __restrict__ W2, const float* __restrict__ b2,
                       const int* __restrict__ y, float* __restrict__ out) {
    __shared__ float cs[288];
    __shared__ float red[8];
    int g = blockIdx.x, t = threadIdx.x;

    for (int i = t; i < 288; i += 128) cs[i] = devPooled[g * 288 + i];
    __syncthreads();

    float acc = b1[t];
#pragma unroll 8
    for (int k = 0; k < 288; k++)
        acc = fmaf(cs[k], W1[k * 128 + t], acc);

    out[2050 + g * 128 + t] = acc;          // feature (pre-ReLU hidden)
    float hr = fmaxf(acc, 0.f);
    float p0 = hr * W2[t * 2 + 0];
    float p1 = hr * W2[t * 2 + 1];
    for (int o = 16; o; o >>= 1) {
        p0 += __shfl_down_sync(0xFFFFFFFFu, p0, o);
        p1 += __shfl_down_sync(0xFFFFFFFFu, p1, o);
    }
    int w = t >> 5;
    if ((t & 31) == 0) { red[w] = p0; red[4 + w] = p1; }
    __syncthreads();

    if (t == 0) {
        float z0 = red[0] + red[1] + red[2] + red[3] + b2[0];
        float z1 = red[4] + red[5] + red[6] + red[7] + b2[1];
        float m  = fmaxf(z0, z1);
        float lse = m + logf(expf(z0 - m) + expf(z1 - m));
        float l0 = z0 - lse, l1 = z1 - lse;
        out[g * 2 + 0] = l0;
        out[g * 2 + 1] = l1;
        int yy = y[g];
        atomicAdd(&out[2048], -(yy ? l1 : l0) * (1.0f / GG));
        int pred = (l1 > l0) ? 1 : 0;
        if (pred == yy) atomicAdd(&out[2049], 1.0f / GG);
    }
}

// ---------------- launch -----------------------------------------------------
extern "C" void kernel_launch(void* const* d_in, const int* in_sizes, int n_in,
                              void* d_out, int out_size) {
    const float* x[3]  = { (const float*)d_in[0], (const float*)d_in[3], (const float*)d_in[6] };
    const int*   ei[3] = { (const int*)  d_in[1], (const int*)  d_in[4], (const int*)  d_in[7] };
    const int*   y     = (const int*)d_in[9];
    const float* Wc[3] = { (const float*)d_in[10], (const float*)d_in[12], (const float*)d_in[14] };
    const float* bc[3] = { (const float*)d_in[11], (const float*)d_in[13], (const float*)d_in[15] };
    const float* W1 = (const float*)d_in[16];
    const float* b1 = (const float*)d_in[17];
    const float* W2 = (const float*)d_in[18];
    const float* b2 = (const float*)d_in[19];
    float* out = (float*)d_out;

    k_head_init<<<1, 1>>>(out);

    for (int b = 0; b < 3; b++) {
        const int* src = ei[b];
        const int* dst = ei[b] + EE;

        k_zero_deg<<<NN / 256, 256>>>();
        k_deg<<<EE / 256, 256>>>(dst);
        k_scan1<<<512, 256>>>();
        k_scan2<<<1, 512>>>();
        k_scan3<<<NN / 256, 256>>>();
        k_csr_fill<<<EE / 256, 256>>>(src, dst);

        k_gemm128<<<NN / 128, 256>>>(x[b], Wc[0]);                     // -> devG0

        int nblk = (NN * 32) / 256;
        k_aggr<true> <<<nblk, 256>>>(bc[0], Wc[1], b * 96 +  0, 0);    // G0 -> G1
        k_aggr<true> <<<nblk, 256>>>(bc[1], Wc[2], b * 96 + 32, 1);    // G1 -> G0
        k_aggr<false><<<nblk, 256>>>(bc[2], nullptr, b * 96 + 64, 0);  // G0 read-only
    }

    k_head<<<GG, 128>>>(W1, b1, W2, b2, y, out);
}

// round 4
// speedup vs baseline: 2.6851x; 1.5517x over previous
#include <cuda_runtime.h>

#define NN 131072
#define GG 1024
#define EE 4194304
#define CAP 49152          // frontier capacity per branch (mean ~33.8k, >80 sigma margin)

// ---------------- scratch (device globals; no allocation allowed) ----------
__device__ float devDis[3][NN];
__device__ int   devDeg[3][NN];
__device__ int   devOff[3][NN];
__device__ int   devCur[3][NN];        // fill cursor; == segment end after fill
__device__ int   devBlk[3][512];
__device__ int   devCsr[3][EE];
__device__ float devG0[3][NN * 32];
__device__ float devG1[3][NN * 32];
__device__ int   devFront[3][CAP];
__device__ int   devFCnt[3];
__device__ float devPooled[GG * 288];

// ---------------- zero (deg, frontier counters, loss/acc slots) -------------
__global__ void k_zero(float* out) {
    int i = blockIdx.x * blockDim.x + threadIdx.x;   // 3*NN threads
    ((int*)devDeg)[i] = 0;
    if (i < 3) devFCnt[i] = 0;
    if (i == 0) { out[2048] = 0.f; out[2049] = 0.f; }
}

// ---------------- degree (int4-vectorized, all branches) --------------------
__global__ void k_deg(const int* __restrict__ d0, const int* __restrict__ d1,
                      const int* __restrict__ d2) {
    int tid = blockIdx.x * blockDim.x + threadIdx.x;  // 3*EE/4 threads
    int b = tid / (EE / 4);
    int i = tid - b * (EE / 4);
    const int* dp = (b == 0) ? d0 : (b == 1) ? d1 : d2;
    int4 d = ((const int4*)dp)[i];
    int* deg = devDeg[b];
    atomicAdd(&deg[d.x], 1); atomicAdd(&deg[d.y], 1);
    atomicAdd(&deg[d.z], 1); atomicAdd(&deg[d.w], 1);
}

// ---------------- scan (per-branch, merged grids) ----------------------------
__global__ void k_scan1() {               // 3*512 blocks x 256
    __shared__ int sh[256];
    int b = blockIdx.x >> 9, j = blockIdx.x & 511;
    int tid = threadIdx.x;
    int i = j * 256 + tid;
    int v = devDeg[b][i];
    sh[tid] = v;
    __syncthreads();
#pragma unroll
    for (int o = 1; o < 256; o <<= 1) {
        int t = (tid >= o) ? sh[tid - o] : 0;
        __syncthreads();
        sh[tid] += t;
        __syncthreads();
    }
    devOff[b][i] = sh[tid] - v;
    if (tid == 255) devBlk[b][j] = sh[255];
}

__global__ void k_scan2() {               // 3 blocks x 512
    __shared__ int sh[512];
    int b = blockIdx.x, tid = threadIdx.x;
    int v = devBlk[b][tid];
    sh[tid] = v;
    __syncthreads();
#pragma unroll
    for (int o = 1; o < 512; o <<= 1) {
        int t = (tid >= o) ? sh[tid - o] : 0;
        __syncthreads();
        sh[tid] += t;
        __syncthreads();
    }
    devBlk[b][tid] = sh[tid] - v;
}

__global__ void k_scan3() {               // 3*NN threads
    int gi = blockIdx.x * blockDim.x + threadIdx.x;
    int b = gi >> 17, i = gi & (NN - 1);
    int off = devOff[b][i] + devBlk[b][i >> 8];
    devOff[b][i] = off;
    devCur[b][i] = off;
    devDis[b][i] = rsqrtf((float)(devDeg[b][i] + 1));
}

// ---------------- CSR fill (int4-vectorized, all branches) -------------------
__global__ void k_csr_fill(const int* __restrict__ s0, const int* __restrict__ d0,
                           const int* __restrict__ s1, const int* __restrict__ d1,
                           const int* __restrict__ s2, const int* __restrict__ d2) {
    int tid = blockIdx.x * blockDim.x + threadIdx.x;  // 3*EE/4 threads
    int b = tid / (EE / 4);
    int i = tid - b * (EE / 4);
    const int* sp = (b == 0) ? s0 : (b == 1) ? s1 : s2;
    const int* dp = (b == 0) ? d0 : (b == 1) ? d1 : d2;
    int4 s = ((const int4*)sp)[i];
    int4 d = ((const int4*)dp)[i];
    int* cur = devCur[b];
    int* csr = devCsr[b];
    csr[atomicAdd(&cur[d.x], 1)] = s.x;
    csr[atomicAdd(&cur[d.y], 1)] = s.y;
    csr[atomicAdd(&cur[d.z], 1)] = s.z;
    csr[atomicAdd(&cur[d.w], 1)] = s.w;
}

// ---------------- first-layer GEMM: devG0[b] = dis * (x @ Wc0) ---------------
__global__ void k_gemm128(const float* __restrict__ x0, const float* __restrict__ x1,
                          const float* __restrict__ x2, const float* __restrict__ W) {
    __shared__ float Ws[128 * 32];
    __shared__ float xs[128 * 33];

    int b = blockIdx.x >> 10;
    int blk = blockIdx.x & 1023;
    const float* x = (b == 0) ? x0 : (b == 1) ? x1 : x2;

    int tid = threadIdx.x;
    int rowbase = blk * 128;

    for (int i = tid; i < 128 * 32 / 4; i += 256)
        ((float4*)Ws)[i] = ((const float4*)W)[i];

    int tx = tid & 7, ty = tid >> 3;
    float4 acc[4];
#pragma unroll
    for (int m = 0; m < 4; m++) acc[m] = make_float4(0.f, 0.f, 0.f, 0.f);

    for (int c = 0; c < 4; c++) {
        for (int r = tid >> 3; r < 128; r += 32) {
            float4 v = *(const float4*)&x[(rowbase + r) * 128 + c * 32 + (tid & 7) * 4];
            float* p = &xs[r * 33 + (tid & 7) * 4];
            p[0] = v.x; p[1] = v.y; p[2] = v.z; p[3] = v.w;
        }
        __syncthreads();
#pragma unroll
        for (int k = 0; k < 32; k++) {
            float4 w = ((const float4*)&Ws[(c * 32 + k) * 32])[tx];
#pragma unroll
            for (int m = 0; m < 4; m++) {
                float xv = xs[(ty + 32 * m) * 33 + k];
                acc[m].x = fmaf(xv, w.x, acc[m].x);
                acc[m].y = fmaf(xv, w.y, acc[m].y);
                acc[m].z = fmaf(xv, w.z, acc[m].z);
                acc[m].w = fmaf(xv, w.w, acc[m].w);
            }
        }
        __syncthreads();
    }

#pragma unroll
    for (int m = 0; m < 4; m++) {
        int row = rowbase + ty + 32 * m;
        float s = devDis[b][row];
        acc[m].x *= s; acc[m].y *= s; acc[m].z *= s; acc[m].w *= s;
        ((float4*)devG0[b])[row * 8 + tx] = acc[m];
    }
}

// ---------------- warp aggregation helper ------------------------------------
__device__ __forceinline__ float warp_aggr(const float* __restrict__ gin,
                                           const int* __restrict__ csr,
                                           int n, int off, int end, int lane) {
    float a0 = gin[n * 32 + lane];        // self-loop (dis*h folded)
    float a1 = 0.f, a2 = 0.f, a3 = 0.f;
    for (int base = off; base < end; base += 32) {
        int p = base + lane;
        int idx = (p < end) ? csr[p] : 0;
        int cnt = min(end - base, 32);
        int j = 0;
        for (; j + 3 < cnt; j += 4) {
            int s0 = __shfl_sync(0xFFFFFFFFu, idx, j);
            int s1 = __shfl_sync(0xFFFFFFFFu, idx, j + 1);
            int s2 = __shfl_sync(0xFFFFFFFFu, idx, j + 2);
            int s3 = __shfl_sync(0xFFFFFFFFu, idx, j + 3);
            a0 += gin[s0 * 32 + lane];
            a1 += gin[s1 * 32 + lane];
            a2 += gin[s2 * 32 + lane];
            a3 += gin[s3 * 32 + lane];
        }
        for (; j < cnt; j++) {
            int s = __shfl_sync(0xFFFFFFFFu, idx, j);
            a0 += gin[s * 32 + lane];
        }
    }
    return (a0 + a1) + (a2 + a3);
}

// ---------------- pass 1: full-node aggr + tanh + matvec(Wc1) + pool ---------
__global__ void k_pass1(const float* __restrict__ bias, const float* __restrict__ Wn) {
    __shared__ float Ws[32 * 32];
    for (int i = threadIdx.x; i < 256; i += 256) ((float4*)Ws)[i] = ((const float4*)Wn)[i];
    __syncthreads();

    int b = blockIdx.x / 16384;
    int local = blockIdx.x - b * 16384;
    int n = local * 8 + (threadIdx.x >> 5);
    int lane = threadIdx.x & 31;

    int off = devOff[b][n];
    int end = devCur[b][n];
    float sum = warp_aggr(devG0[b], devCsr[b], n, off, end, lane);

    float dis = devDis[b][n];
    float v = tanhf(dis * sum + bias[lane]);

    if ((n & 127) == 0)
        devPooled[(n >> 7) * 288 + b * 96 + lane] = v;

    float acc = 0.f;
#pragma unroll
    for (int k = 0; k < 32; k++) {
        float vk = __shfl_sync(0xFFFFFFFFu, v, k);
        acc = fmaf(vk, Ws[k * 32 + lane], acc);
    }
    devG1[b][n * 32 + lane] = dis * acc;
}

// ---------------- frontier build: srcs of pooled nodes + pooled --------------
__global__ void k_frontier() {            // 3*128 blocks x 256 (warp per pooled node)
    int b = blockIdx.x / 128;
    int w = (blockIdx.x - b * 128) * 8 + (threadIdx.x >> 5);
    int lane = threadIdx.x & 31;
    int n = w * 128;                      // pooled node

    int off = devOff[b][n];
    int len = devCur[b][n] - off;

    int base;
    if (lane == 0) base = atomicAdd(&devFCnt[b], len + 1);
    base = __shfl_sync(0xFFFFFFFFu, base, 0);
    if (base + len + 1 > CAP) return;     // statistically impossible; OOB guard

    for (int i = lane; i < len; i += 32)
        devFront[b][base + i] = devCsr[b][off + i];
    if (lane == 0) devFront[b][base + len] = n;
}

// ---------------- pass 2: frontier-only aggr + tanh + matvec(Wc2) + pool -----
__global__ void k_pass2(const float* __restrict__ bias, const float* __restrict__ Wn) {
    __shared__ float Ws[32 * 32];
    for (int i = threadIdx.x; i < 256; i += 256) ((float4*)Ws)[i] = ((const float4*)Wn)[i];
    __syncthreads();

    int b = blockIdx.x / 600;             // 3*600 blocks
    int wid = (blockIdx.x - b * 600) * 8 + (threadIdx.x >> 5);
    int lane = threadIdx.x & 31;
    int cnt = devFCnt[b];

    const float* gin = devG1[b];
    float* gout = devG0[b];
    const int* csr = devCsr[b];

    for (int id = wid; id < cnt; id += 600 * 8) {
        int n = devFront[b][id];
        int off = devOff[b][n];
        int end = devCur[b][n];
        float sum = warp_aggr(gin, csr, n, off, end, lane);
        float dis = devDis[b][n];
        float v = tanhf(dis * sum + bias[lane]);

        if ((n & 127) == 0)
            devPooled[(n >> 7) * 288 + b * 96 + 32 + lane] = v;

        float acc = 0.f;
#pragma unroll
        for (int k = 0; k < 32; k++) {
            float vk = __shfl_sync(0xFFFFFFFFu, v, k);
            acc = fmaf(vk, Ws[k * 32 + lane], acc);
        }
        gout[n * 32 + lane] = dis * acc;
    }
}

// ---------------- pass 3: pooled-only aggr + tanh + pool ---------------------
__global__ void k_pass3(const float* __restrict__ bias) {  // 3*128 blocks x 256
    int b = blockIdx.x / 128;
    int w = (blockIdx.x - b * 128) * 8 + (threadIdx.x >> 5);
    int lane = threadIdx.x & 31;
    int n = w * 128;                      // pooled node

    int off = devOff[b][n];
    int end = devCur[b][n];
    float sum = warp_aggr(devG0[b], devCsr[b], n, off, end, lane);
    float v = tanhf(devDis[b][n] * sum + bias[lane]);
    devPooled[(n >> 7) * 288 + b * 96 + 64 + lane] = v;
}

// ---------------- head -------------------------------------------------------
__global__ void k_head(const float* __restrict__ W1, const float* __restrict__ b1,
                       const float* __restrict__ W2, const float* __restrict__ b2,
                       const int* __restrict__ y, float* __restrict__ out) {
    __shared__ float cs[288];
    __shared__ float red[8];
    int g = blockIdx.x, t = threadIdx.x;

    for (int i = t; i < 288; i += 128) cs[i] = devPooled[g * 288 + i];
    __syncthreads();

    float acc = b1[t];
#pragma unroll 8
    for (int k = 0; k < 288; k++)
        acc = fmaf(cs[k], W1[k * 128 + t], acc);

    out[2050 + g * 128 + t] = acc;          // feature (pre-ReLU hidden)
    float hr = fmaxf(acc, 0.f);
    float p0 = hr * W2[t * 2 + 0];
    float p1 = hr * W2[t * 2 + 1];
    for (int o = 16; o; o >>= 1) {
        p0 += __shfl_down_sync(0xFFFFFFFFu, p0, o);
        p1 += __shfl_down_sync(0xFFFFFFFFu, p1, o);
    }
    int w = t >> 5;
    if ((t & 31) == 0) { red[w] = p0; red[4 + w] = p1; }
    __syncthreads();

    if (t == 0) {
        float z0 = red[0] + red[1] + red[2] + red[3] + b2[0];
        float z1 = red[4] + red[5] + red[6] + red[7] + b2[1];
        float m  = fmaxf(z0, z1);
        float lse = m + logf(expf(z0 - m) + expf(z1 - m));
        float l0 = z0 - lse, l1 = z1 - lse;
        out[g * 2 + 0] = l0;
        out[g * 2 + 1] = l1;
        int yy = y[g];
        atomicAdd(&out[2048], -(yy ? l1 : l0) * (1.0f / GG));
        int pred = (l1 > l0) ? 1 : 0;
        if (pred == yy) atomicAdd(&out[2049], 1.0f / GG);
    }
}

// ---------------- launch -----------------------------------------------------
extern "C" void kernel_launch(void* const* d_in, const int* in_sizes, int n_in,
                              void* d_out, int out_size) {
    const float* x0 = (const float*)d_in[0];
    const float* x1 = (const float*)d_in[3];
    const float* x2 = (const float*)d_in[6];
    const int* s0 = (const int*)d_in[1]; const int* d0 = s0 + EE;
    const int* s1 = (const int*)d_in[4]; const int* d1 = s1 + EE;
    const int* s2 = (const int*)d_in[7]; const int* d2 = s2 + EE;
    const int* y = (const int*)d_in[9];
    const float* Wc0 = (const float*)d_in[10]; const float* bc0 = (const float*)d_in[11];
    const float* Wc1 = (const float*)d_in[12]; const float* bc1 = (const float*)d_in[13];
    const float* Wc2 = (const float*)d_in[14]; const float* bc2 = (const float*)d_in[15];
    const float* W1 = (const float*)d_in[16]; const float* b1 = (const float*)d_in[17];
    const float* W2 = (const float*)d_in[18]; const float* b2 = (const float*)d_in[19];
    float* out = (float*)d_out;

    k_zero<<<3 * NN / 256, 256>>>(out);
    k_deg<<<3 * (EE / 4) / 256, 256>>>(d0, d1, d2);
    k_scan1<<<3 * 512, 256>>>();
    k_scan2<<<3, 512>>>();
    k_scan3<<<3 * NN / 256, 256>>>();
    k_csr_fill<<<3 * (EE / 4) / 256, 256>>>(s0, d0, s1, d1, s2, d2);
    k_gemm128<<<3 * 1024, 256>>>(x0, x1, x2, Wc0);
    k_pass1<<<3 * 16384, 256>>>(bc0, Wc1);
    k_frontier<<<3 * 128, 256>>>();
    k_pass2<<<3 * 600, 256>>>(bc1, Wc2);
    k_pass3<<<3 * 128, 256>>>(bc2);
    k_head<<<GG, 128>>>(W1, b1, W2, b2, y, out);
}